// round 3
// baseline (speedup 1.0000x reference)
#include <cuda_runtime.h>
#include <cuda_bf16.h>
#include <cstdint>

#define SCALE_F 0.08838834764831845f

// ---------------- scratch (device globals; no allocation allowed) ----------------
__device__ __nv_bfloat16 g_Xb[4096 * 1024];          // X in bf16
__device__ __nv_bfloat16 g_Wb[24 * 1024 * 128];      // [Wq(8) | Wk(8) | Wv(8)] bf16
__device__ __nv_bfloat16 g_Qb[8 * 4096 * 128];       // Q bf16 [h][n][e]
__device__ __nv_bfloat16 g_Kb[8 * 4096 * 128];       // K bf16 [h][m][e]
__device__ float         g_Vf[8 * 4096 * 128];       // V f32  [h][m][e]
__device__ __nv_bfloat16 g_Vs[8 * 4096 * 128];       // V/colsum bf16
__device__ float         g_colsum[8 * 4096];         // sum_n exp(scale*q_n.k_m)

// ---------------- helpers ----------------
__device__ __forceinline__ uint32_t smem_u32(const void* p) {
    return (uint32_t)__cvta_generic_to_shared(p);
}

__device__ __forceinline__ void ldsm4(uint32_t a, uint32_t& r0, uint32_t& r1,
                                      uint32_t& r2, uint32_t& r3) {
    asm volatile("ldmatrix.sync.aligned.m8n8.x4.shared.b16 {%0,%1,%2,%3}, [%4];"
                 : "=r"(r0), "=r"(r1), "=r"(r2), "=r"(r3) : "r"(a));
}
__device__ __forceinline__ void ldsm4t(uint32_t a, uint32_t& r0, uint32_t& r1,
                                       uint32_t& r2, uint32_t& r3) {
    asm volatile("ldmatrix.sync.aligned.m8n8.x4.trans.shared.b16 {%0,%1,%2,%3}, [%4];"
                 : "=r"(r0), "=r"(r1), "=r"(r2), "=r"(r3) : "r"(a));
}

// mma.m16n8k16 row.col f32 += bf16*bf16
__device__ __forceinline__ void mma16816(float c[4], uint32_t a0, uint32_t a1,
                                         uint32_t a2, uint32_t a3,
                                         uint32_t b0, uint32_t b1) {
    asm volatile(
        "mma.sync.aligned.m16n8k16.row.col.f32.bf16.bf16.f32 "
        "{%0,%1,%2,%3},{%4,%5,%6,%7},{%8,%9},{%0,%1,%2,%3};"
        : "+f"(c[0]), "+f"(c[1]), "+f"(c[2]), "+f"(c[3])
        : "r"(a0), "r"(a1), "r"(a2), "r"(a3), "r"(b0), "r"(b1));
}

// Address patterns for ldmatrix x4 (lane -> row of one 8x8 matrix).
// Pattern A: matrices ordered (r0,c0),(r0+8,c0),(r0,c0+8),(r0+8,c0+8)
//   used for: A-frag (non-trans) from row-major [row][k] tile,
//             B-frag (trans)     from row-major [k][col] tile.
__device__ __forceinline__ uint32_t lm_addrA(uint32_t base, int ld, int row0, int col0, int lane) {
    int r = row0 + (lane & 7) + ((lane >> 3) & 1) * 8;
    int c = col0 + (lane >> 4) * 8;
    return base + (uint32_t)(r * ld + c) * 2u;
}
// Pattern B: matrices ordered (r0,c0),(r0,c0+8),(r0+8,c0),(r0+8,c0+8)
//   used for: B-frag (non-trans) from "n-major" tile (i.e. B^T stored row-major:
//             smem rows = output cols, smem cols = k).
__device__ __forceinline__ uint32_t lm_addrB(uint32_t base, int ld, int row0, int col0, int lane) {
    int r = row0 + (lane & 7) + (lane >> 4) * 8;
    int c = col0 + ((lane >> 3) & 1) * 8;
    return base + (uint32_t)(r * ld + c) * 2u;
}

__device__ __forceinline__ uint32_t pack_bf2(float lo, float hi) {
    __nv_bfloat162 p = __floats2bfloat162_rn(lo, hi);
    return *reinterpret_cast<uint32_t*>(&p);
}
__device__ __forceinline__ float sigmoidf_(float x) {
    return 1.0f / (1.0f + __expf(-x));
}

// ---------------- kernel 0: f32 -> bf16 conversions ----------------
__global__ void cvt_kernel(const float* __restrict__ X, const float* __restrict__ Wq,
                           const float* __restrict__ Wk, const float* __restrict__ Wv) {
    int stride = gridDim.x * blockDim.x;
    for (int i = blockIdx.x * blockDim.x + threadIdx.x; i < 4096 * 1024; i += stride)
        g_Xb[i] = __float2bfloat16(X[i]);
    for (int i = blockIdx.x * blockDim.x + threadIdx.x; i < 8 * 1024 * 128; i += stride) {
        g_Wb[i]               = __float2bfloat16(Wq[i]);
        g_Wb[1048576 + i]     = __float2bfloat16(Wk[i]);
        g_Wb[2097152 + i]     = __float2bfloat16(Wv[i]);
    }
}

// ---------------- kernel 1: batched projections ----------------
// grid (32 n-tiles, 24 gemms). C[n,e] = X[n,:] @ W_g[:,e] + bias_g[e]
#define PLD_A 40    // 32 + 8 pad (keeps ldmatrix 16B-aligned + conflict-free)
#define PLD_B 136   // 128 + 8 pad

__global__ __launch_bounds__(256) void proj_kernel(const float* __restrict__ bq,
                                                   const float* __restrict__ bk,
                                                   const float* __restrict__ bv) {
    __shared__ __nv_bfloat16 As[128 * PLD_A];
    __shared__ __nv_bfloat16 Bs[32 * PLD_B];
    const int g = blockIdx.y;           // 0..23
    const int n0 = blockIdx.x * 128;
    const int tid = threadIdx.x, lane = tid & 31, warp = tid >> 5;
    const __nv_bfloat16* Wg = g_Wb + g * (1024 * 128);
    const uint32_t sA = smem_u32(As), sB = smem_u32(Bs);

    float acc[16][4];
#pragma unroll
    for (int t = 0; t < 16; t++)
#pragma unroll
        for (int j = 0; j < 4; j++) acc[t][j] = 0.f;

    for (int k0 = 0; k0 < 1024; k0 += 32) {
#pragma unroll
        for (int i = 0; i < 4; i++) {            // A tile 128x32
            int idx = tid + 256 * i;
            int row = idx >> 3, cv = (idx & 7) * 4;
            *(uint2*)&As[row * PLD_A + cv] =
                *(const uint2*)&g_Xb[(n0 + row) * 1024 + k0 + cv];
        }
#pragma unroll
        for (int i = 0; i < 4; i++) {            // B tile 32x128
            int idx = tid + 256 * i;
            int row = idx >> 5, cv = (idx & 31) * 4;
            *(uint2*)&Bs[row * PLD_B + cv] =
                *(const uint2*)&Wg[(k0 + row) * 128 + cv];
        }
        __syncthreads();
#pragma unroll
        for (int kk = 0; kk < 32; kk += 16) {
            uint32_t a0, a1, a2, a3;
            ldsm4(lm_addrA(sA, PLD_A, warp * 16, kk, lane), a0, a1, a2, a3);
#pragma unroll
            for (int nt = 0; nt < 8; nt++) {
                uint32_t b0, b1, b2, b3;
                ldsm4t(lm_addrA(sB, PLD_B, kk, nt * 16, lane), b0, b1, b2, b3);
                mma16816(acc[2 * nt],     a0, a1, a2, a3, b0, b1);
                mma16816(acc[2 * nt + 1], a0, a1, a2, a3, b2, b3);
            }
        }
        __syncthreads();
    }

    const int h = g & 7, qkv = g >> 3;
    const float* bias = (qkv == 0 ? bq : qkv == 1 ? bk : bv) + h * 128;
#pragma unroll
    for (int t = 0; t < 16; t++) {
        int col = t * 8 + (lane & 3) * 2;
        int row = n0 + warp * 16 + (lane >> 2);
        float v0 = acc[t][0] + bias[col];
        float v1 = acc[t][1] + bias[col + 1];
        float v2 = acc[t][2] + bias[col];
        float v3 = acc[t][3] + bias[col + 1];
        int o0 = (h * 4096 + row) * 128 + col;
        int o1 = (h * 4096 + row + 8) * 128 + col;
        if (qkv == 0) {
            *(uint32_t*)&g_Qb[o0] = pack_bf2(v0, v1);
            *(uint32_t*)&g_Qb[o1] = pack_bf2(v2, v3);
        } else if (qkv == 1) {
            *(uint32_t*)&g_Kb[o0] = pack_bf2(v0, v1);
            *(uint32_t*)&g_Kb[o1] = pack_bf2(v2, v3);
        } else {
            *(float2*)&g_Vf[o0] = make_float2(v0, v1);
            *(float2*)&g_Vf[o1] = make_float2(v2, v3);
        }
    }
}

// ---------------- kernel 2: column sums of exp(score) ----------------
// S'[m][n] = K[m].Q[n]; colsum[m] = sum_n exp(SCALE * S')
// grid (32 m-tiles, 8 heads). smem: Ks[128][136] persistent, Qs[128][136] streamed.
__global__ __launch_bounds__(256) void colsum_kernel() {
    extern __shared__ __nv_bfloat16 smA[];
    __nv_bfloat16* Ks = smA;
    __nv_bfloat16* Qs = smA + 128 * 136;
    const int h = blockIdx.y, m0 = blockIdx.x * 128;
    const int tid = threadIdx.x, lane = tid & 31, warp = tid >> 5;
    const __nv_bfloat16* K = g_Kb + h * (4096 * 128);
    const __nv_bfloat16* Q = g_Qb + h * (4096 * 128);
    const uint32_t sK = smem_u32(Ks), sQ = smem_u32(Qs);

#pragma unroll
    for (int i = 0; i < 16; i++) {               // K tile 128x128 (persistent)
        int idx = tid + 256 * i;
        int row = idx >> 5, cv = (idx & 31) * 4;
        *(uint2*)&Ks[row * 136 + cv] = *(const uint2*)&K[(m0 + row) * 128 + cv];
    }

    float rs0 = 0.f, rs1 = 0.f;
    for (int n0 = 0; n0 < 4096; n0 += 128) {
        __syncthreads();
#pragma unroll
        for (int i = 0; i < 16; i++) {           // Q tile 128x128
            int idx = tid + 256 * i;
            int row = idx >> 5, cv = (idx & 31) * 4;
            *(uint2*)&Qs[row * 136 + cv] = *(const uint2*)&Q[(n0 + row) * 128 + cv];
        }
        __syncthreads();

        float sacc[16][4];
#pragma unroll
        for (int t = 0; t < 16; t++)
#pragma unroll
            for (int j = 0; j < 4; j++) sacc[t][j] = 0.f;

#pragma unroll
        for (int kk = 0; kk < 8; kk++) {
            uint32_t a0, a1, a2, a3;
            ldsm4(lm_addrA(sK, 136, warp * 16, kk * 16, lane), a0, a1, a2, a3);
#pragma unroll
            for (int nt = 0; nt < 8; nt++) {
                uint32_t b0, b1, b2, b3;
                ldsm4(lm_addrB(sQ, 136, nt * 16, kk * 16, lane), b0, b1, b2, b3);
                mma16816(sacc[2 * nt],     a0, a1, a2, a3, b0, b1);
                mma16816(sacc[2 * nt + 1], a0, a1, a2, a3, b2, b3);
            }
        }
#pragma unroll
        for (int t = 0; t < 16; t++) {
            rs0 += __expf(sacc[t][0] * SCALE_F) + __expf(sacc[t][1] * SCALE_F);
            rs1 += __expf(sacc[t][2] * SCALE_F) + __expf(sacc[t][3] * SCALE_F);
        }
    }
    rs0 += __shfl_xor_sync(0xffffffffu, rs0, 1);
    rs0 += __shfl_xor_sync(0xffffffffu, rs0, 2);
    rs1 += __shfl_xor_sync(0xffffffffu, rs1, 1);
    rs1 += __shfl_xor_sync(0xffffffffu, rs1, 2);
    if ((lane & 3) == 0) {
        int r = m0 + warp * 16 + (lane >> 2);
        g_colsum[h * 4096 + r]     = rs0;
        g_colsum[h * 4096 + r + 8] = rs1;
    }
}

// ---------------- kernel 3: fold 1/colsum into V ----------------
__global__ void scalev_kernel() {
    int stride = gridDim.x * blockDim.x;
    for (int i = blockIdx.x * blockDim.x + threadIdx.x; i < 8 * 4096 * 128; i += stride) {
        int hm = i >> 7;
        g_Vs[i] = __float2bfloat16(__fdividef(g_Vf[i], g_colsum[hm]));
    }
}

// ---------------- kernel 4: Z = exp(QK^T)*V', sigmoid ----------------
// grid (32 n-tiles, 8 heads).
__global__ __launch_bounds__(256, 1) void attn_kernel(float* __restrict__ out) {
    extern __shared__ __nv_bfloat16 smB[];
    __nv_bfloat16* Qs = smB;                  // 128x136 persistent
    __nv_bfloat16* Ks = smB + 128 * 136;      // streamed
    __nv_bfloat16* Vs = smB + 2 * 128 * 136;  // streamed
    const int h = blockIdx.y, n0 = blockIdx.x * 128;
    const int tid = threadIdx.x, lane = tid & 31, warp = tid >> 5;
    const __nv_bfloat16* Q = g_Qb + h * (4096 * 128);
    const __nv_bfloat16* K = g_Kb + h * (4096 * 128);
    const __nv_bfloat16* V = g_Vs + h * (4096 * 128);
    const uint32_t sQ = smem_u32(Qs), sK = smem_u32(Ks), sV = smem_u32(Vs);

#pragma unroll
    for (int i = 0; i < 16; i++) {               // Q tile (persistent)
        int idx = tid + 256 * i;
        int row = idx >> 5, cv = (idx & 31) * 4;
        *(uint2*)&Qs[row * 136 + cv] = *(const uint2*)&Q[(n0 + row) * 128 + cv];
    }

    float zacc[16][4];
#pragma unroll
    for (int t = 0; t < 16; t++)
#pragma unroll
        for (int j = 0; j < 4; j++) zacc[t][j] = 0.f;

    for (int m0 = 0; m0 < 4096; m0 += 128) {
        __syncthreads();
#pragma unroll
        for (int i = 0; i < 16; i++) {
            int idx = tid + 256 * i;
            int row = idx >> 5, cv = (idx & 31) * 4;
            *(uint2*)&Ks[row * 136 + cv] = *(const uint2*)&K[(m0 + row) * 128 + cv];
        }
#pragma unroll
        for (int i = 0; i < 16; i++) {
            int idx = tid + 256 * i;
            int row = idx >> 5, cv = (idx & 31) * 4;
            *(uint2*)&Vs[row * 136 + cv] = *(const uint2*)&V[(m0 + row) * 128 + cv];
        }
        __syncthreads();

        // S = Q K^T for this (n-tile, m-tile)
        float sacc[16][4];
#pragma unroll
        for (int t = 0; t < 16; t++)
#pragma unroll
            for (int j = 0; j < 4; j++) sacc[t][j] = 0.f;

#pragma unroll
        for (int kk = 0; kk < 8; kk++) {
            uint32_t a0, a1, a2, a3;
            ldsm4(lm_addrA(sQ, 136, warp * 16, kk * 16, lane), a0, a1, a2, a3);
#pragma unroll
            for (int nt = 0; nt < 8; nt++) {
                uint32_t b0, b1, b2, b3;
                ldsm4(lm_addrB(sK, 136, nt * 16, kk * 16, lane), b0, b1, b2, b3);
                mma16816(sacc[2 * nt],     a0, a1, a2, a3, b0, b1);
                mma16816(sacc[2 * nt + 1], a0, a1, a2, a3, b2, b3);
            }
        }

        // P = exp(SCALE*S) packed into A-fragments (C-frag layout == A-frag layout)
        uint32_t pf[8][4];
#pragma unroll
        for (int j = 0; j < 8; j++) {
            pf[j][0] = pack_bf2(__expf(sacc[2 * j][0] * SCALE_F),
                                __expf(sacc[2 * j][1] * SCALE_F));
            pf[j][1] = pack_bf2(__expf(sacc[2 * j][2] * SCALE_F),
                                __expf(sacc[2 * j][3] * SCALE_F));
            pf[j][2] = pack_bf2(__expf(sacc[2 * j + 1][0] * SCALE_F),
                                __expf(sacc[2 * j + 1][1] * SCALE_F));
            pf[j][3] = pack_bf2(__expf(sacc[2 * j + 1][2] * SCALE_F),
                                __expf(sacc[2 * j + 1][3] * SCALE_F));
        }

        // Z += P @ V'  (k = m dimension)
#pragma unroll
        for (int j = 0; j < 8; j++) {
#pragma unroll
            for (int et = 0; et < 8; et++) {
                uint32_t b0, b1, b2, b3;
                ldsm4t(lm_addrA(sV, 136, j * 16, et * 16, lane), b0, b1, b2, b3);
                mma16816(zacc[2 * et],     pf[j][0], pf[j][1], pf[j][2], pf[j][3], b0, b1);
                mma16816(zacc[2 * et + 1], pf[j][0], pf[j][1], pf[j][2], pf[j][3], b2, b3);
            }
        }
    }

    // epilogue: sigmoid, write out[n][h*128+e]
#pragma unroll
    for (int t = 0; t < 16; t++) {
        int col = h * 128 + t * 8 + (lane & 3) * 2;
        int row = n0 + warp * 16 + (lane >> 2);
        *(float2*)&out[row * 1024 + col] =
            make_float2(sigmoidf_(zacc[t][0]), sigmoidf_(zacc[t][1]));
        *(float2*)&out[(row + 8) * 1024 + col] =
            make_float2(sigmoidf_(zacc[t][2]), sigmoidf_(zacc[t][3]));
    }
}

// ---------------- launch ----------------
extern "C" void kernel_launch(void* const* d_in, const int* in_sizes, int n_in,
                              void* d_out, int out_size) {
    const float* X  = (const float*)d_in[0];
    const float* Wq = (const float*)d_in[1];
    const float* bq = (const float*)d_in[2];
    const float* Wk = (const float*)d_in[3];
    const float* bk = (const float*)d_in[4];
    const float* Wv = (const float*)d_in[5];
    const float* bv = (const float*)d_in[6];
    float* out = (float*)d_out;

    cudaFuncSetAttribute(colsum_kernel, cudaFuncAttributeMaxDynamicSharedMemorySize,
                         2 * 128 * 136 * 2);
    cudaFuncSetAttribute(attn_kernel, cudaFuncAttributeMaxDynamicSharedMemorySize,
                         3 * 128 * 136 * 2);

    cvt_kernel<<<2048, 256>>>(X, Wq, Wk, Wv);
    proj_kernel<<<dim3(32, 24), 256>>>(bq, bk, bv);
    colsum_kernel<<<dim3(32, 8), 256, 2 * 128 * 136 * 2>>>();
    scalev_kernel<<<2048, 256>>>();
    attn_kernel<<<dim3(32, 8), 256, 3 * 128 * 136 * 2>>>(out);
}

// round 5
// speedup vs baseline: 1.5663x; 1.5663x over previous
#include <cuda_runtime.h>
#include <cuda_bf16.h>
#include <cuda_fp8.h>
#include <cstdint>

#define SCALE_F 0.08838834764831845f
#define SW128(x) ((x) ^ (((x) >> 3) & 0x70))

// ---------------- scratch ----------------
__device__ uint8_t       g_Xf8[4096 * 1024];        // X e4m3 [n][d]
__device__ uint8_t       g_Wt8[24 * 128 * 1024];    // W e4m3 transposed [g][e][d]
__device__ uint8_t       g_Qf8[8 * 4096 * 128];     // Q e4m3 [h][n][e]
__device__ uint8_t       g_Kf8[8 * 4096 * 128];     // K e4m3 [h][m][e]
__device__ float         g_Vf[8 * 4096 * 128];      // V f32  [h][m][e]
__device__ __nv_bfloat16 g_Vs[8 * 4096 * 128];      // V/colsum bf16
__device__ float         g_colsum[8 * 4096];

// ---------------- helpers ----------------
__device__ __forceinline__ uint32_t smem_u32(const void* p) {
    return (uint32_t)__cvta_generic_to_shared(p);
}
__device__ __forceinline__ uint32_t pack_bf2(float lo, float hi) {
    __nv_bfloat162 p = __floats2bfloat162_rn(lo, hi);
    return *reinterpret_cast<uint32_t*>(&p);
}
__device__ __forceinline__ float sigmoidf_(float x) { return 1.0f / (1.0f + __expf(-x)); }
__device__ __forceinline__ uint16_t f8x2(float a, float b) {
    return (uint16_t)__nv_cvt_float2_to_fp8x2(make_float2(a, b), __NV_SATFINITE, __NV_E4M3);
}

#define CPA16(s, g) asm volatile("cp.async.cg.shared.global [%0], [%1], 16;" :: "r"(s), "l"(g))
#define CP_COMMIT() asm volatile("cp.async.commit_group;" ::: "memory")
#define CP_WAIT1()  asm volatile("cp.async.wait_group 1;" ::: "memory")

// ldmatrix (b16 view; works on fp8 bytes too)
__device__ __forceinline__ void ldsm4(uint32_t a, uint32_t& r0, uint32_t& r1, uint32_t& r2, uint32_t& r3) {
    asm volatile("ldmatrix.sync.aligned.m8n8.x4.shared.b16 {%0,%1,%2,%3}, [%4];"
                 : "=r"(r0), "=r"(r1), "=r"(r2), "=r"(r3) : "r"(a));
}
__device__ __forceinline__ void ldsm4t(uint32_t a, uint32_t& r0, uint32_t& r1, uint32_t& r2, uint32_t& r3) {
    asm volatile("ldmatrix.sync.aligned.m8n8.x4.trans.shared.b16 {%0,%1,%2,%3}, [%4];"
                 : "=r"(r0), "=r"(r1), "=r"(r2), "=r"(r3) : "r"(a));
}
// bf16 mma (PV)
__device__ __forceinline__ void mma16816(float c[4], uint32_t a0, uint32_t a1, uint32_t a2, uint32_t a3,
                                         uint32_t b0, uint32_t b1) {
    asm volatile("mma.sync.aligned.m16n8k16.row.col.f32.bf16.bf16.f32 "
        "{%0,%1,%2,%3},{%4,%5,%6,%7},{%8,%9},{%0,%1,%2,%3};"
        : "+f"(c[0]), "+f"(c[1]), "+f"(c[2]), "+f"(c[3])
        : "r"(a0), "r"(a1), "r"(a2), "r"(a3), "r"(b0), "r"(b1));
}
// fp8 e4m3 mma (scores/proj)
__device__ __forceinline__ void mma_f8(float c[4], uint32_t a0, uint32_t a1, uint32_t a2, uint32_t a3,
                                       uint32_t b0, uint32_t b1) {
    asm volatile("mma.sync.aligned.m16n8k32.row.col.f32.e4m3.e4m3.f32 "
        "{%0,%1,%2,%3},{%4,%5,%6,%7},{%8,%9},{%0,%1,%2,%3};"
        : "+f"(c[0]), "+f"(c[1]), "+f"(c[2]), "+f"(c[3])
        : "r"(a0), "r"(a1), "r"(a2), "r"(a3), "r"(b0), "r"(b1));
}

// fp8 swizzled tile (rows x 128B) ldmatrix addressing: kk = 32-byte k-step
__device__ __forceinline__ uint32_t lmA8(uint32_t base, int r0, int kk, int lane) {
    int r = r0 + (lane & 7) + ((lane >> 3) & 1) * 8;
    int c16 = kk * 2 + (lane >> 4);
    return base + SW128((uint32_t)((r << 7) + (c16 << 4)));
}
__device__ __forceinline__ uint32_t lmB8(uint32_t base, int r0, int kk, int lane) {
    int r = r0 + (lane & 7) + (lane >> 4) * 8;
    int c16 = kk * 2 + ((lane >> 3) & 1);
    return base + SW128((uint32_t)((r << 7) + (c16 << 4)));
}
// bf16 V-tile ldmatrix (padded linear layout, ld in b16 elems)
__device__ __forceinline__ uint32_t lm_addrA(uint32_t base, int ld, int row0, int col0, int lane) {
    int r = row0 + (lane & 7) + ((lane >> 3) & 1) * 8;
    int c = col0 + (lane >> 4) * 8;
    return base + (uint32_t)(r * ld + c) * 2u;
}

// loaders: fp8 tile rows x 128B (swizzled dst); bf16 V tile rows x 256B (272B stride)
__device__ __forceinline__ void cpa8(uint32_t dst, const uint8_t* src, int ldb, int rows, int tid) {
    for (int o = tid; o < rows * 8; o += 256) {
        int r = o >> 3, c = o & 7;
        CPA16(dst + SW128((uint32_t)((r << 7) + (c << 4))), src + (size_t)r * ldb + c * 16);
    }
}
__device__ __forceinline__ void cpaV(uint32_t dst, const __nv_bfloat16* src, int rows, int tid) {
    for (int o = tid; o < rows * 16; o += 256) {
        int r = o >> 4, c = o & 15;
        CPA16(dst + (uint32_t)(r * 272 + c * 16), (const char*)src + (size_t)r * 256 + c * 16);
    }
}

// ---------------- cvt X -> fp8 ----------------
__global__ void cvtX_kernel(const float* __restrict__ X) {
    int st = gridDim.x * blockDim.x;
    for (int o = blockIdx.x * blockDim.x + threadIdx.x; o < 1048576; o += st) {
        float4 v = ((const float4*)X)[o];
        ((uint32_t*)g_Xf8)[o] = (uint32_t)f8x2(v.x, v.y) | ((uint32_t)f8x2(v.z, v.w) << 16);
    }
}

// ---------------- cvt W -> fp8 transposed [g][e][d] ----------------
__global__ __launch_bounds__(256) void cvtW_kernel(const float* __restrict__ Wq,
                                                   const float* __restrict__ Wk,
                                                   const float* __restrict__ Wv) {
    __shared__ uint8_t t[64][96];
    const int g = blockIdx.z, d0 = blockIdx.x * 64, e0 = blockIdx.y * 64;
    const float* W = (g < 8 ? Wq : g < 16 ? Wk : Wv) + (size_t)(g & 7) * 131072;
    for (int o = threadIdx.x; o < 1024; o += 256) {
        int i = o >> 4, j4 = (o & 15) * 4;
        float4 v = *(const float4*)&W[(size_t)(d0 + i) * 128 + e0 + j4];
        t[j4 + 0][i] = (uint8_t)__nv_cvt_float_to_fp8(v.x, __NV_SATFINITE, __NV_E4M3);
        t[j4 + 1][i] = (uint8_t)__nv_cvt_float_to_fp8(v.y, __NV_SATFINITE, __NV_E4M3);
        t[j4 + 2][i] = (uint8_t)__nv_cvt_float_to_fp8(v.z, __NV_SATFINITE, __NV_E4M3);
        t[j4 + 3][i] = (uint8_t)__nv_cvt_float_to_fp8(v.w, __NV_SATFINITE, __NV_E4M3);
    }
    __syncthreads();
    for (int o = threadIdx.x; o < 256; o += 256) {
        int r = o >> 2, c = (o & 3) * 16;
        *(uint4*)&g_Wt8[(size_t)g * 131072 + (size_t)(e0 + r) * 1024 + d0 + c] = *(uint4*)&t[r][c];
    }
}

// ---------------- proj: C = X @ W_g + b (fp8 mma, k=1024) ----------------
#define PJ_A(b) ((b) * 16384)
#define PJ_B(b) (32768 + (b) * 16384)
__global__ __launch_bounds__(256, 2) void proj_kernel(const float* __restrict__ bq,
                                                      const float* __restrict__ bk,
                                                      const float* __restrict__ bv) {
    extern __shared__ char sm[];
    const uint32_t sb = smem_u32(sm);
    const int g = blockIdx.y, n0 = blockIdx.x * 128;
    const int tid = threadIdx.x, lane = tid & 31, warp = tid >> 5;
    const uint8_t* Xp = g_Xf8 + (size_t)n0 * 1024;
    const uint8_t* Wp = g_Wt8 + (size_t)g * 131072;
    cpa8(sb + PJ_A(0), Xp, 1024, 128, tid);
    cpa8(sb + PJ_B(0), Wp, 1024, 128, tid);
    CP_COMMIT();
    cpa8(sb + PJ_A(1), Xp + 128, 1024, 128, tid);
    cpa8(sb + PJ_B(1), Wp + 128, 1024, 128, tid);
    CP_COMMIT();
    float acc[16][4];
#pragma unroll
    for (int t = 0; t < 16; t++) { acc[t][0] = acc[t][1] = acc[t][2] = acc[t][3] = 0.f; }
    for (int i = 0; i < 8; i++) {
        const int b = i & 1;
        CP_WAIT1();
        __syncthreads();
#pragma unroll
        for (int kk = 0; kk < 4; kk++) {
            uint32_t a0, a1, a2, a3;
            ldsm4(lmA8(sb + PJ_A(b), warp * 16, kk, lane), a0, a1, a2, a3);
#pragma unroll
            for (int nt = 0; nt < 8; nt++) {
                uint32_t b0, b1, b2, b3;
                ldsm4(lmB8(sb + PJ_B(b), nt * 16, kk, lane), b0, b1, b2, b3);
                mma_f8(acc[2 * nt], a0, a1, a2, a3, b0, b1);
                mma_f8(acc[2 * nt + 1], a0, a1, a2, a3, b2, b3);
            }
        }
        __syncthreads();
        if (i < 6) {
            cpa8(sb + PJ_A(b), Xp + (i + 2) * 128, 1024, 128, tid);
            cpa8(sb + PJ_B(b), Wp + (i + 2) * 128, 1024, 128, tid);
        }
        CP_COMMIT();
    }
    const int h = g & 7, qkv = g >> 3;
    const float* bias = (qkv == 0 ? bq : qkv == 1 ? bk : bv) + h * 128;
#pragma unroll
    for (int t = 0; t < 16; t++) {
        int col = t * 8 + (lane & 3) * 2, row = n0 + warp * 16 + (lane >> 2);
        float v0 = acc[t][0] + bias[col], v1 = acc[t][1] + bias[col + 1];
        float v2 = acc[t][2] + bias[col], v3 = acc[t][3] + bias[col + 1];
        int o0 = (h * 4096 + row) * 128 + col, o1 = (h * 4096 + row + 8) * 128 + col;
        if (qkv == 0) {
            *(uint16_t*)&g_Qf8[o0] = f8x2(v0, v1); *(uint16_t*)&g_Qf8[o1] = f8x2(v2, v3);
        } else if (qkv == 1) {
            *(uint16_t*)&g_Kf8[o0] = f8x2(v0, v1); *(uint16_t*)&g_Kf8[o1] = f8x2(v2, v3);
        } else {
            *(float2*)&g_Vf[o0] = make_float2(v0, v1); *(float2*)&g_Vf[o1] = make_float2(v2, v3);
        }
    }
}

// ---------------- colsum: S'[m][n] = K.Q^T fp8; colsum[m] = sum_n exp ----------------
#define CS_K 0
#define CS_Q(b) (16384 + (b) * 16384)
__global__ __launch_bounds__(256, 2) void colsum_kernel() {
    extern __shared__ char sm[];
    const uint32_t sb = smem_u32(sm);
    const int h = blockIdx.y, m0 = blockIdx.x * 128;
    const int tid = threadIdx.x, lane = tid & 31, warp = tid >> 5;
    const uint8_t* K = g_Kf8 + (size_t)h * 524288 + (size_t)m0 * 128;
    const uint8_t* Q = g_Qf8 + (size_t)h * 524288;
    cpa8(sb + CS_K, K, 128, 128, tid);
    cpa8(sb + CS_Q(0), Q, 128, 128, tid);
    CP_COMMIT();
    cpa8(sb + CS_Q(1), Q + 16384, 128, 128, tid);
    CP_COMMIT();
    float rs0 = 0.f, rs1 = 0.f;
    for (int i = 0; i < 32; i++) {
        const int b = i & 1;
        CP_WAIT1();
        __syncthreads();
        float sacc[16][4];
#pragma unroll
        for (int t = 0; t < 16; t++) { sacc[t][0] = sacc[t][1] = sacc[t][2] = sacc[t][3] = 0.f; }
#pragma unroll
        for (int kk = 0; kk < 4; kk++) {
            uint32_t a0, a1, a2, a3;
            ldsm4(lmA8(sb + CS_K, warp * 16, kk, lane), a0, a1, a2, a3);
#pragma unroll
            for (int nt = 0; nt < 8; nt++) {
                uint32_t b0, b1, b2, b3;
                ldsm4(lmB8(sb + CS_Q(b), nt * 16, kk, lane), b0, b1, b2, b3);
                mma_f8(sacc[2 * nt], a0, a1, a2, a3, b0, b1);
                mma_f8(sacc[2 * nt + 1], a0, a1, a2, a3, b2, b3);
            }
        }
#pragma unroll
        for (int t = 0; t < 16; t++) {
            rs0 += __expf(sacc[t][0] * SCALE_F) + __expf(sacc[t][1] * SCALE_F);
            rs1 += __expf(sacc[t][2] * SCALE_F) + __expf(sacc[t][3] * SCALE_F);
        }
        __syncthreads();
        if (i < 30) cpa8(sb + CS_Q(b), Q + (size_t)(i + 2) * 16384, 128, 128, tid);
        CP_COMMIT();
    }
    rs0 += __shfl_xor_sync(0xffffffffu, rs0, 1);
    rs0 += __shfl_xor_sync(0xffffffffu, rs0, 2);
    rs1 += __shfl_xor_sync(0xffffffffu, rs1, 1);
    rs1 += __shfl_xor_sync(0xffffffffu, rs1, 2);
    if ((lane & 3) == 0) {
        int r = m0 + warp * 16 + (lane >> 2);
        g_colsum[h * 4096 + r] = rs0;
        g_colsum[h * 4096 + r + 8] = rs1;
    }
}

// ---------------- scalev: Vs = V / colsum (bf16) ----------------
__global__ void scalev_kernel() {
    int st = gridDim.x * blockDim.x;
    for (int i = blockIdx.x * blockDim.x + threadIdx.x; i < 8 * 4096 * 128; i += st) {
        int hm = i >> 7;
        g_Vs[i] = __float2bfloat16(__fdividef(g_Vf[i], g_colsum[hm]));
    }
}

// ---------------- attn: S = Q.K^T fp8; P = exp; Z += P@Vs bf16; sigmoid ----------------
#define AT_Q 0
#define AT_K(b) (16384 + (b) * 8192)
#define AT_V(b) (32768 + (b) * 17408)
__global__ __launch_bounds__(256, 2) void attn_kernel(float* __restrict__ out) {
    extern __shared__ char sm[];
    const uint32_t sb = smem_u32(sm);
    const int h = blockIdx.y, n0 = blockIdx.x * 128;
    const int tid = threadIdx.x, lane = tid & 31, warp = tid >> 5;
    const uint8_t* Q = g_Qf8 + (size_t)h * 524288 + (size_t)n0 * 128;
    const uint8_t* K = g_Kf8 + (size_t)h * 524288;
    const __nv_bfloat16* V = g_Vs + (size_t)h * 524288;
    cpa8(sb + AT_Q, Q, 128, 128, tid);
    cpa8(sb + AT_K(0), K, 128, 64, tid);
    cpaV(sb + AT_V(0), V, 64, tid);
    CP_COMMIT();
    cpa8(sb + AT_K(1), K + 8192, 128, 64, tid);
    cpaV(sb + AT_V(1), V + 8192, 64, tid);
    CP_COMMIT();
    float zacc[16][4];
#pragma unroll
    for (int t = 0; t < 16; t++) { zacc[t][0] = zacc[t][1] = zacc[t][2] = zacc[t][3] = 0.f; }
    for (int i = 0; i < 64; i++) {
        const int b = i & 1;
        CP_WAIT1();
        __syncthreads();
        float sacc[8][4];
#pragma unroll
        for (int t = 0; t < 8; t++) { sacc[t][0] = sacc[t][1] = sacc[t][2] = sacc[t][3] = 0.f; }
#pragma unroll
        for (int kk = 0; kk < 4; kk++) {
            uint32_t a0, a1, a2, a3;
            ldsm4(lmA8(sb + AT_Q, warp * 16, kk, lane), a0, a1, a2, a3);
#pragma unroll
            for (int nt = 0; nt < 4; nt++) {
                uint32_t b0, b1, b2, b3;
                ldsm4(lmB8(sb + AT_K(b), nt * 16, kk, lane), b0, b1, b2, b3);
                mma_f8(sacc[2 * nt], a0, a1, a2, a3, b0, b1);
                mma_f8(sacc[2 * nt + 1], a0, a1, a2, a3, b2, b3);
            }
        }
        uint32_t pf[4][4];
#pragma unroll
        for (int j = 0; j < 4; j++) {
            pf[j][0] = pack_bf2(__expf(sacc[2 * j][0] * SCALE_F), __expf(sacc[2 * j][1] * SCALE_F));
            pf[j][1] = pack_bf2(__expf(sacc[2 * j][2] * SCALE_F), __expf(sacc[2 * j][3] * SCALE_F));
            pf[j][2] = pack_bf2(__expf(sacc[2 * j + 1][0] * SCALE_F), __expf(sacc[2 * j + 1][1] * SCALE_F));
            pf[j][3] = pack_bf2(__expf(sacc[2 * j + 1][2] * SCALE_F), __expf(sacc[2 * j + 1][3] * SCALE_F));
        }
#pragma unroll
        for (int j = 0; j < 4; j++) {
#pragma unroll
            for (int et = 0; et < 8; et++) {
                uint32_t b0, b1, b2, b3;
                ldsm4t(lm_addrA(sb + AT_V(b), 136, j * 16, et * 16, lane), b0, b1, b2, b3);
                mma16816(zacc[2 * et], pf[j][0], pf[j][1], pf[j][2], pf[j][3], b0, b1);
                mma16816(zacc[2 * et + 1], pf[j][0], pf[j][1], pf[j][2], pf[j][3], b2, b3);
            }
        }
        __syncthreads();
        if (i < 62) {
            cpa8(sb + AT_K(b), K + (size_t)(i + 2) * 8192, 128, 64, tid);
            cpaV(sb + AT_V(b), V + (size_t)(i + 2) * 8192, 64, tid);
        }
        CP_COMMIT();
    }
#pragma unroll
    for (int t = 0; t < 16; t++) {
        int col = h * 128 + t * 8 + (lane & 3) * 2;
        int row = n0 + warp * 16 + (lane >> 2);
        *(float2*)&out[(size_t)row * 1024 + col] =
            make_float2(sigmoidf_(zacc[t][0]), sigmoidf_(zacc[t][1]));
        *(float2*)&out[(size_t)(row + 8) * 1024 + col] =
            make_float2(sigmoidf_(zacc[t][2]), sigmoidf_(zacc[t][3]));
    }
}

// ---------------- launch ----------------
extern "C" void kernel_launch(void* const* d_in, const int* in_sizes, int n_in,
                              void* d_out, int out_size) {
    const float* X  = (const float*)d_in[0];
    const float* Wq = (const float*)d_in[1];
    const float* bq = (const float*)d_in[2];
    const float* Wk = (const float*)d_in[3];
    const float* bk = (const float*)d_in[4];
    const float* Wv = (const float*)d_in[5];
    const float* bv = (const float*)d_in[6];
    float* out = (float*)d_out;

    cudaFuncSetAttribute(proj_kernel, cudaFuncAttributeMaxDynamicSharedMemorySize, 65536);
    cudaFuncSetAttribute(colsum_kernel, cudaFuncAttributeMaxDynamicSharedMemorySize, 49152);
    cudaFuncSetAttribute(attn_kernel, cudaFuncAttributeMaxDynamicSharedMemorySize, 67584);

    cvtX_kernel<<<1024, 256>>>(X);
    cvtW_kernel<<<dim3(16, 2, 24), 256>>>(Wq, Wk, Wv);
    proj_kernel<<<dim3(32, 24), 256, 65536>>>(bq, bk, bv);
    colsum_kernel<<<dim3(32, 8), 256, 49152>>>();
    scalev_kernel<<<2048, 256>>>();
    attn_kernel<<<dim3(32, 8), 256, 67584>>>(out);
}

// round 6
// speedup vs baseline: 1.7492x; 1.1168x over previous
#include <cuda_runtime.h>
#include <cuda_bf16.h>
#include <cuda_fp8.h>
#include <cstdint>

#define SCALE_F 0.08838834764831845f
#define SW128(x) ((x) ^ (((x) >> 3) & 0x70))

// ---------------- scratch ----------------
__device__ uint8_t       g_Xf8[4096 * 1024];        // X e4m3 [n][d]
__device__ uint8_t       g_Wt8[24 * 128 * 1024];    // W e4m3 transposed [g][e][d]
__device__ uint8_t       g_Qf8[8 * 4096 * 128];     // Q e4m3 [h][n][e]
__device__ uint8_t       g_Kf8[8 * 4096 * 128];     // K e4m3 [h][m][e]
__device__ float         g_Vf[8 * 4096 * 128];      // V f32  [h][m][e]
__device__ __nv_bfloat16 g_Vs[8 * 4096 * 128];      // V/colsum bf16
__device__ float         g_colsum[8 * 4096];
__device__ __nv_bfloat16 g_Pt[8ull * 4096 * 4096];  // P^T = exp(scale*S)[h][m][n]

// ---------------- helpers ----------------
__device__ __forceinline__ uint32_t smem_u32(const void* p) {
    return (uint32_t)__cvta_generic_to_shared(p);
}
__device__ __forceinline__ uint32_t pack_bf2(float lo, float hi) {
    __nv_bfloat162 p = __floats2bfloat162_rn(lo, hi);
    return *reinterpret_cast<uint32_t*>(&p);
}
__device__ __forceinline__ float sigmoidf_(float x) { return 1.0f / (1.0f + __expf(-x)); }
__device__ __forceinline__ uint16_t f8x2(float a, float b) {
    return (uint16_t)__nv_cvt_float2_to_fp8x2(make_float2(a, b), __NV_SATFINITE, __NV_E4M3);
}

#define CPA16(s, g) asm volatile("cp.async.cg.shared.global [%0], [%1], 16;" :: "r"(s), "l"(g))
#define CP_COMMIT() asm volatile("cp.async.commit_group;" ::: "memory")
#define CP_WAIT1()  asm volatile("cp.async.wait_group 1;" ::: "memory")

__device__ __forceinline__ void ldsm4(uint32_t a, uint32_t& r0, uint32_t& r1, uint32_t& r2, uint32_t& r3) {
    asm volatile("ldmatrix.sync.aligned.m8n8.x4.shared.b16 {%0,%1,%2,%3}, [%4];"
                 : "=r"(r0), "=r"(r1), "=r"(r2), "=r"(r3) : "r"(a));
}
__device__ __forceinline__ void ldsm4t(uint32_t a, uint32_t& r0, uint32_t& r1, uint32_t& r2, uint32_t& r3) {
    asm volatile("ldmatrix.sync.aligned.m8n8.x4.trans.shared.b16 {%0,%1,%2,%3}, [%4];"
                 : "=r"(r0), "=r"(r1), "=r"(r2), "=r"(r3) : "r"(a));
}
__device__ __forceinline__ void mma16816(float c[4], uint32_t a0, uint32_t a1, uint32_t a2, uint32_t a3,
                                         uint32_t b0, uint32_t b1) {
    asm volatile("mma.sync.aligned.m16n8k16.row.col.f32.bf16.bf16.f32 "
        "{%0,%1,%2,%3},{%4,%5,%6,%7},{%8,%9},{%0,%1,%2,%3};"
        : "+f"(c[0]), "+f"(c[1]), "+f"(c[2]), "+f"(c[3])
        : "r"(a0), "r"(a1), "r"(a2), "r"(a3), "r"(b0), "r"(b1));
}
__device__ __forceinline__ void mma_f8(float c[4], uint32_t a0, uint32_t a1, uint32_t a2, uint32_t a3,
                                       uint32_t b0, uint32_t b1) {
    asm volatile("mma.sync.aligned.m16n8k32.row.col.f32.e4m3.e4m3.f32 "
        "{%0,%1,%2,%3},{%4,%5,%6,%7},{%8,%9},{%0,%1,%2,%3};"
        : "+f"(c[0]), "+f"(c[1]), "+f"(c[2]), "+f"(c[3])
        : "r"(a0), "r"(a1), "r"(a2), "r"(a3), "r"(b0), "r"(b1));
}

// fp8 swizzled tile (rows x 128B) ldmatrix addressing: kk = 32-byte k-step
__device__ __forceinline__ uint32_t lmA8(uint32_t base, int r0, int kk, int lane) {
    int r = r0 + (lane & 7) + ((lane >> 3) & 1) * 8;
    int c16 = kk * 2 + (lane >> 4);
    return base + SW128((uint32_t)((r << 7) + (c16 << 4)));
}
__device__ __forceinline__ uint32_t lmB8(uint32_t base, int r0, int kk, int lane) {
    int r = r0 + (lane & 7) + (lane >> 4) * 8;
    int c16 = kk * 2 + ((lane >> 3) & 1);
    return base + SW128((uint32_t)((r << 7) + (c16 << 4)));
}
// bf16 linear tile (ld elems): pattern A (B-frags via trans)
__device__ __forceinline__ uint32_t lm_addrA(uint32_t base, int ld, int row0, int col0, int lane) {
    int r = row0 + (lane & 7) + ((lane >> 3) & 1) * 8;
    int c = col0 + (lane >> 4) * 8;
    return base + (uint32_t)(r * ld + c) * 2u;
}
// bf16 linear tile: pattern B (A-frags from [k][n] storage via trans)
__device__ __forceinline__ uint32_t lm_addrB(uint32_t base, int ld, int row0, int col0, int lane) {
    int r = row0 + (lane & 7) + (lane >> 4) * 8;
    int c = col0 + ((lane >> 3) & 1) * 8;
    return base + (uint32_t)(r * ld + c) * 2u;
}

// loaders
__device__ __forceinline__ void cpa8(uint32_t dst, const uint8_t* src, int ldb, int rows, int tid) {
    for (int o = tid; o < rows * 8; o += 256) {
        int r = o >> 3, c = o & 7;
        CPA16(dst + SW128((uint32_t)((r << 7) + (c << 4))), src + (size_t)r * ldb + c * 16);
    }
}
// 64 x 128 bf16, global row stride ldel elems -> smem 272B rows
__device__ __forceinline__ void cpaB(uint32_t dst, const __nv_bfloat16* src, int ldel, int tid) {
    for (int o = tid; o < 1024; o += 256) {
        int r = o >> 4, c = o & 15;
        CPA16(dst + (uint32_t)(r * 272 + c * 16), (const char*)(src + (size_t)r * ldel) + c * 16);
    }
}

// ---------------- cvt X -> fp8 ----------------
__global__ void cvtX_kernel(const float* __restrict__ X) {
    int st = gridDim.x * blockDim.x;
    for (int o = blockIdx.x * blockDim.x + threadIdx.x; o < 1048576; o += st) {
        float4 v = ((const float4*)X)[o];
        ((uint32_t*)g_Xf8)[o] = (uint32_t)f8x2(v.x, v.y) | ((uint32_t)f8x2(v.z, v.w) << 16);
    }
}

// ---------------- cvt W -> fp8 transposed [g][e][d] ----------------
__global__ __launch_bounds__(256) void cvtW_kernel(const float* __restrict__ Wq,
                                                   const float* __restrict__ Wk,
                                                   const float* __restrict__ Wv) {
    __shared__ uint8_t t[64][96];
    const int g = blockIdx.z, d0 = blockIdx.x * 64, e0 = blockIdx.y * 64;
    const float* W = (g < 8 ? Wq : g < 16 ? Wk : Wv) + (size_t)(g & 7) * 131072;
    for (int o = threadIdx.x; o < 1024; o += 256) {
        int i = o >> 4, j4 = (o & 15) * 4;
        float4 v = *(const float4*)&W[(size_t)(d0 + i) * 128 + e0 + j4];
        t[j4 + 0][i] = (uint8_t)__nv_cvt_float_to_fp8(v.x, __NV_SATFINITE, __NV_E4M3);
        t[j4 + 1][i] = (uint8_t)__nv_cvt_float_to_fp8(v.y, __NV_SATFINITE, __NV_E4M3);
        t[j4 + 2][i] = (uint8_t)__nv_cvt_float_to_fp8(v.z, __NV_SATFINITE, __NV_E4M3);
        t[j4 + 3][i] = (uint8_t)__nv_cvt_float_to_fp8(v.w, __NV_SATFINITE, __NV_E4M3);
    }
    __syncthreads();
    for (int o = threadIdx.x; o < 256; o += 256) {
        int r = o >> 2, c = (o & 3) * 16;
        *(uint4*)&g_Wt8[(size_t)g * 131072 + (size_t)(e0 + r) * 1024 + d0 + c] = *(uint4*)&t[r][c];
    }
}

// ---------------- proj: C = X @ W_g + b (fp8 mma, k=1024) ----------------
#define PJ_A(b) ((b) * 16384)
#define PJ_B(b) (32768 + (b) * 16384)
__global__ __launch_bounds__(256, 2) void proj_kernel(const float* __restrict__ bq,
                                                      const float* __restrict__ bk,
                                                      const float* __restrict__ bv) {
    extern __shared__ char sm[];
    const uint32_t sb = smem_u32(sm);
    const int g = blockIdx.y, n0 = blockIdx.x * 128;
    const int tid = threadIdx.x, lane = tid & 31, warp = tid >> 5;
    const uint8_t* Xp = g_Xf8 + (size_t)n0 * 1024;
    const uint8_t* Wp = g_Wt8 + (size_t)g * 131072;
    cpa8(sb + PJ_A(0), Xp, 1024, 128, tid);
    cpa8(sb + PJ_B(0), Wp, 1024, 128, tid);
    CP_COMMIT();
    cpa8(sb + PJ_A(1), Xp + 128, 1024, 128, tid);
    cpa8(sb + PJ_B(1), Wp + 128, 1024, 128, tid);
    CP_COMMIT();
    float acc[16][4];
#pragma unroll
    for (int t = 0; t < 16; t++) { acc[t][0] = acc[t][1] = acc[t][2] = acc[t][3] = 0.f; }
    for (int i = 0; i < 8; i++) {
        const int b = i & 1;
        CP_WAIT1();
        __syncthreads();
#pragma unroll
        for (int kk = 0; kk < 4; kk++) {
            uint32_t a0, a1, a2, a3;
            ldsm4(lmA8(sb + PJ_A(b), warp * 16, kk, lane), a0, a1, a2, a3);
#pragma unroll
            for (int nt = 0; nt < 8; nt++) {
                uint32_t b0, b1, b2, b3;
                ldsm4(lmB8(sb + PJ_B(b), nt * 16, kk, lane), b0, b1, b2, b3);
                mma_f8(acc[2 * nt], a0, a1, a2, a3, b0, b1);
                mma_f8(acc[2 * nt + 1], a0, a1, a2, a3, b2, b3);
            }
        }
        __syncthreads();
        if (i < 6) {
            cpa8(sb + PJ_A(b), Xp + (i + 2) * 128, 1024, 128, tid);
            cpa8(sb + PJ_B(b), Wp + (i + 2) * 128, 1024, 128, tid);
        }
        CP_COMMIT();
    }
    const int h = g & 7, qkv = g >> 3;
    const float* bias = (qkv == 0 ? bq : qkv == 1 ? bk : bv) + h * 128;
#pragma unroll
    for (int t = 0; t < 16; t++) {
        int col = t * 8 + (lane & 3) * 2, row = n0 + warp * 16 + (lane >> 2);
        float v0 = acc[t][0] + bias[col], v1 = acc[t][1] + bias[col + 1];
        float v2 = acc[t][2] + bias[col], v3 = acc[t][3] + bias[col + 1];
        int o0 = (h * 4096 + row) * 128 + col, o1 = (h * 4096 + row + 8) * 128 + col;
        if (qkv == 0) {
            *(uint16_t*)&g_Qf8[o0] = f8x2(v0, v1); *(uint16_t*)&g_Qf8[o1] = f8x2(v2, v3);
        } else if (qkv == 1) {
            *(uint16_t*)&g_Kf8[o0] = f8x2(v0, v1); *(uint16_t*)&g_Kf8[o1] = f8x2(v2, v3);
        } else {
            *(float2*)&g_Vf[o0] = make_float2(v0, v1); *(float2*)&g_Vf[o1] = make_float2(v2, v3);
        }
    }
}

// ---- scoreP: S'[m][n] = K.Q^T fp8; P = exp -> g_Pt bf16; colsum[m] = rowsum(P) ----
#define CS_K 0
#define CS_Q(b) (16384 + (b) * 16384)
__global__ __launch_bounds__(256, 2) void scoreP_kernel() {
    extern __shared__ char sm[];
    const uint32_t sb = smem_u32(sm);
    const int h = blockIdx.y, m0 = blockIdx.x * 128;
    const int tid = threadIdx.x, lane = tid & 31, warp = tid >> 5;
    const uint8_t* K = g_Kf8 + (size_t)h * 524288 + (size_t)m0 * 128;
    const uint8_t* Q = g_Qf8 + (size_t)h * 524288;
    cpa8(sb + CS_K, K, 128, 128, tid);
    cpa8(sb + CS_Q(0), Q, 128, 128, tid);
    CP_COMMIT();
    cpa8(sb + CS_Q(1), Q + 16384, 128, 128, tid);
    CP_COMMIT();
    CP_WAIT1();                       // group0 (K + Q0) done
    __syncthreads();
    uint32_t kf[4][4];                // persistent K fragments, hoisted
#pragma unroll
    for (int kk = 0; kk < 4; kk++)
        ldsm4(lmA8(sb + CS_K, warp * 16, kk, lane), kf[kk][0], kf[kk][1], kf[kk][2], kf[kk][3]);
    float rs0 = 0.f, rs1 = 0.f;
    const size_t pr = (size_t)h * 16777216 + (size_t)(m0 + warp * 16 + (lane >> 2)) * 4096
                      + (size_t)((lane & 3) * 2);
    for (int i = 0; i < 32; i++) {
        const int b = i & 1;
        CP_WAIT1();
        __syncthreads();
        float sacc[16][4];
#pragma unroll
        for (int t = 0; t < 16; t++) { sacc[t][0] = sacc[t][1] = sacc[t][2] = sacc[t][3] = 0.f; }
#pragma unroll
        for (int kk = 0; kk < 4; kk++) {
#pragma unroll
            for (int nt = 0; nt < 8; nt++) {
                uint32_t b0, b1, b2, b3;
                ldsm4(lmB8(sb + CS_Q(b), nt * 16, kk, lane), b0, b1, b2, b3);
                mma_f8(sacc[2 * nt], kf[kk][0], kf[kk][1], kf[kk][2], kf[kk][3], b0, b1);
                mma_f8(sacc[2 * nt + 1], kf[kk][0], kf[kk][1], kf[kk][2], kf[kk][3], b2, b3);
            }
        }
        const size_t pb = pr + (size_t)i * 128;
#pragma unroll
        for (int t = 0; t < 16; t++) {
            float e0 = __expf(sacc[t][0] * SCALE_F), e1 = __expf(sacc[t][1] * SCALE_F);
            float e2 = __expf(sacc[t][2] * SCALE_F), e3 = __expf(sacc[t][3] * SCALE_F);
            rs0 += e0 + e1;
            rs1 += e2 + e3;
            *(uint32_t*)&g_Pt[pb + t * 8]            = pack_bf2(e0, e1);
            *(uint32_t*)&g_Pt[pb + 8 * 4096 + t * 8] = pack_bf2(e2, e3);
        }
        __syncthreads();
        if (i < 30) cpa8(sb + CS_Q(b), Q + (size_t)(i + 2) * 16384, 128, 128, tid);
        CP_COMMIT();
    }
    rs0 += __shfl_xor_sync(0xffffffffu, rs0, 1);
    rs0 += __shfl_xor_sync(0xffffffffu, rs0, 2);
    rs1 += __shfl_xor_sync(0xffffffffu, rs1, 1);
    rs1 += __shfl_xor_sync(0xffffffffu, rs1, 2);
    if ((lane & 3) == 0) {
        int r = m0 + warp * 16 + (lane >> 2);
        g_colsum[h * 4096 + r] = rs0;
        g_colsum[h * 4096 + r + 8] = rs1;
    }
}

// ---------------- scalev: Vs = V / colsum (bf16) ----------------
__global__ void scalev_kernel() {
    int st = gridDim.x * blockDim.x;
    for (int i = blockIdx.x * blockDim.x + threadIdx.x; i < 8 * 4096 * 128; i += st) {
        int hm = i >> 7;
        g_Vs[i] = __float2bfloat16(__fdividef(g_Vf[i], g_colsum[hm]));
    }
}

// ---------------- pv: Z[n][e] = sum_m Pt[m][n] * Vs[m][e]; sigmoid ----------------
#define PV_P(b) ((b) * 17408)
#define PV_V(b) (34816 + (b) * 17408)
__global__ __launch_bounds__(256, 2) void pv_kernel(float* __restrict__ out) {
    extern __shared__ char sm[];
    const uint32_t sb = smem_u32(sm);
    const int h = blockIdx.y, n0 = blockIdx.x * 128;
    const int tid = threadIdx.x, lane = tid & 31, warp = tid >> 5;
    const __nv_bfloat16* P = g_Pt + (size_t)h * 16777216 + n0;   // rows m (stride 4096)
    const __nv_bfloat16* V = g_Vs + (size_t)h * 524288;          // rows m (stride 128)
    cpaB(sb + PV_P(0), P, 4096, tid);
    cpaB(sb + PV_V(0), V, 128, tid);
    CP_COMMIT();
    cpaB(sb + PV_P(1), P + (size_t)64 * 4096, 4096, tid);
    cpaB(sb + PV_V(1), V + 64 * 128, 128, tid);
    CP_COMMIT();
    float zacc[16][4];
#pragma unroll
    for (int t = 0; t < 16; t++) { zacc[t][0] = zacc[t][1] = zacc[t][2] = zacc[t][3] = 0.f; }
    for (int i = 0; i < 64; i++) {
        const int b = i & 1;
        CP_WAIT1();
        __syncthreads();
        uint32_t af[4][4];                     // A-frags: Pt^T tile (n rows, k=m)
#pragma unroll
        for (int kk = 0; kk < 4; kk++)
            ldsm4t(lm_addrB(sb + PV_P(b), 136, kk * 16, warp * 16, lane),
                   af[kk][0], af[kk][1], af[kk][2], af[kk][3]);
#pragma unroll
        for (int kk = 0; kk < 4; kk++) {
#pragma unroll
            for (int et = 0; et < 8; et++) {
                uint32_t b0, b1, b2, b3;
                ldsm4t(lm_addrA(sb + PV_V(b), 136, kk * 16, et * 16, lane), b0, b1, b2, b3);
                mma16816(zacc[2 * et], af[kk][0], af[kk][1], af[kk][2], af[kk][3], b0, b1);
                mma16816(zacc[2 * et + 1], af[kk][0], af[kk][1], af[kk][2], af[kk][3], b2, b3);
            }
        }
        __syncthreads();
        if (i < 62) {
            cpaB(sb + PV_P(b), P + (size_t)(i + 2) * 64 * 4096, 4096, tid);
            cpaB(sb + PV_V(b), V + (size_t)(i + 2) * 64 * 128, 128, tid);
        }
        CP_COMMIT();
    }
#pragma unroll
    for (int t = 0; t < 16; t++) {
        int col = h * 128 + t * 8 + (lane & 3) * 2;
        int row = n0 + warp * 16 + (lane >> 2);
        *(float2*)&out[(size_t)row * 1024 + col] =
            make_float2(sigmoidf_(zacc[t][0]), sigmoidf_(zacc[t][1]));
        *(float2*)&out[(size_t)(row + 8) * 1024 + col] =
            make_float2(sigmoidf_(zacc[t][2]), sigmoidf_(zacc[t][3]));
    }
}

// ---------------- launch ----------------
extern "C" void kernel_launch(void* const* d_in, const int* in_sizes, int n_in,
                              void* d_out, int out_size) {
    const float* X  = (const float*)d_in[0];
    const float* Wq = (const float*)d_in[1];
    const float* bq = (const float*)d_in[2];
    const float* Wk = (const float*)d_in[3];
    const float* bk = (const float*)d_in[4];
    const float* Wv = (const float*)d_in[5];
    const float* bv = (const float*)d_in[6];
    float* out = (float*)d_out;

    cudaFuncSetAttribute(proj_kernel, cudaFuncAttributeMaxDynamicSharedMemorySize, 65536);
    cudaFuncSetAttribute(scoreP_kernel, cudaFuncAttributeMaxDynamicSharedMemorySize, 49152);
    cudaFuncSetAttribute(pv_kernel, cudaFuncAttributeMaxDynamicSharedMemorySize, 69632);

    cvtX_kernel<<<1024, 256>>>(X);
    cvtW_kernel<<<dim3(16, 2, 24), 256>>>(Wq, Wk, Wv);
    proj_kernel<<<dim3(32, 24), 256, 65536>>>(bq, bk, bv);
    scoreP_kernel<<<dim3(32, 8), 256, 49152>>>();
    scalev_kernel<<<2048, 256>>>();
    pv_kernel<<<dim3(32, 8), 256, 69632>>>(out);
}